// round 2
// baseline (speedup 1.0000x reference)
#include <cuda_runtime.h>
#include <cuda_bf16.h>
#include <math.h>

// ---------------------------------------------------------------------------
// Swin Transformer block: B=16, C=384, H=W=56, NH=12, WS=7, SS=3, MLP=1536
// T = 50176 tokens, NWIN = 1024 windows, N = 49 tokens/window, HD = 32
// ---------------------------------------------------------------------------

#define TOK   50176      // B*H*W
#define CCH   384
#define HH    56
#define WW2   56
#define NWIN  1024       // B * 64
#define NTOK  49
#define NHEAD 12
#define HDIM  32
#define MLPD  1536

// Scratch (device globals — allocation-free rule)
__device__ float g_xbhwc[TOK * CCH];       // raw input transposed to token-major
__device__ float g_xw   [TOK * CCH];       // LN1 + shifted-window partitioned
__device__ float g_q    [TOK * CCH];       // [win, head, n, hd], pre-scaled
__device__ float g_k    [TOK * CCH];
__device__ float g_v    [TOK * CCH];
__device__ float g_ao   [TOK * CCH];       // attention out, [win, n, c]
__device__ float g_x2   [TOK * CCH];       // post-attn residual (token-major BHWC)
__device__ float g_xn2  [TOK * CCH];       // LN2 output
__device__ float g_h1   [TOK * MLPD];      // fc1+gelu output
__device__ float g_y    [TOK * CCH];       // fc2 + residual (token-major)

// ---------------------------------------------------------------------------
// K1: LN1 + NCHW->NHWC transpose + shifted-window partition
// one block per (b, h) row; smem tile [c][w] padded to stride 57
// ---------------------------------------------------------------------------
__global__ void __launch_bounds__(256) k_ln1_window(
    const float* __restrict__ x, const float* __restrict__ g1,
    const float* __restrict__ b1)
{
    extern __shared__ float sm[];               // [384][57]
    __shared__ float smu[56], srs[56];
    const int bh = blockIdx.x;
    const int b = bh / HH, h = bh % HH;
    const int tid = threadIdx.x;
    const float* xp = x + (size_t)b * CCH * (HH * WW2) + (size_t)h * WW2;

    for (int idx = tid; idx < CCH * WW2; idx += 256) {
        int c = idx / WW2, w = idx % WW2;
        sm[c * 57 + w] = xp[(size_t)c * (HH * WW2) + w];
    }
    __syncthreads();

    if (tid < WW2) {
        float s = 0.f, s2 = 0.f;
        for (int c = 0; c < CCH; c++) {
            float t = sm[c * 57 + tid];
            s += t; s2 += t * t;
        }
        float mu = s * (1.0f / CCH);
        float var = s2 * (1.0f / CCH) - mu * mu;
        smu[tid] = mu;
        srs[tid] = rsqrtf(var + 1e-5f);
    }
    __syncthreads();

    // window coords for this h
    int hp = h - 3; if (hp < 0) hp += HH;
    const int wh = hp / 7, rr = hp % 7;

    for (int idx = tid; idx < WW2 * CCH; idx += 256) {
        int w = idx / CCH, c = idx % CCH;
        float val = sm[c * 57 + w];
        size_t tok = (size_t)(b * HH + h) * WW2 + w;
        g_xbhwc[tok * CCH + c] = val;
        float nv = (val - smu[w]) * srs[w] * __ldg(&g1[c]) + __ldg(&b1[c]);
        int wp = w - 3; if (wp < 0) wp += WW2;
        int ww = wp / 7, cc = wp % 7;
        int win = (b * 8 + wh) * 8 + ww;
        int n2 = rr * 7 + cc;
        g_xw[((size_t)win * NTOK + n2) * CCH + c] = nv;
    }
}

// ---------------------------------------------------------------------------
// K2: fp32 tiled GEMM, 128x64x16 tile, 256 threads, 8x4 microtile.
// MODE 0: QKV (split q/k/v into [win,head,n,hd], q pre-scaled)
// MODE 1: proj (window-reverse + unshift + shortcut residual -> g_x2)
// MODE 2: fc1 + exact GELU
// MODE 3: fc2 + x2 residual -> g_y
// ---------------------------------------------------------------------------
template <int MODE>
__global__ void __launch_bounds__(256) k_gemm(
    const float* __restrict__ A, const float* __restrict__ Bw,
    const float* __restrict__ bias, int M, int N, int K)
{
    __shared__ float As[16][132];
    __shared__ float Bs[16][64];

    const int tid = threadIdx.x;
    const int tx = tid & 15, ty = tid >> 4;
    const int m0 = blockIdx.y * 128, n0 = blockIdx.x * 64;

    float acc[8][4];
#pragma unroll
    for (int i = 0; i < 8; i++)
#pragma unroll
        for (int j = 0; j < 4; j++) acc[i][j] = 0.f;

    for (int k0 = 0; k0 < K; k0 += 16) {
        // A tile: 128 rows x 16 cols -> As transposed [k][m]
#pragma unroll
        for (int i = 0; i < 2; i++) {
            int li = i * 256 + tid;          // 0..511
            int row = li >> 2;
            int kk = (li & 3) * 4;
            float4 va = *reinterpret_cast<const float4*>(
                A + (size_t)(m0 + row) * K + k0 + kk);
            As[kk + 0][row] = va.x;
            As[kk + 1][row] = va.y;
            As[kk + 2][row] = va.z;
            As[kk + 3][row] = va.w;
        }
        // B tile: 16 rows x 64 cols
        {
            int kk = tid >> 4;
            int col = (tid & 15) * 4;
            *reinterpret_cast<float4*>(&Bs[kk][col]) =
                *reinterpret_cast<const float4*>(
                    Bw + (size_t)(k0 + kk) * N + n0 + col);
        }
        __syncthreads();
#pragma unroll
        for (int kk = 0; kk < 16; kk++) {
            float a[8], bfr[4];
            *reinterpret_cast<float4*>(&a[0]) =
                *reinterpret_cast<const float4*>(&As[kk][ty * 8]);
            *reinterpret_cast<float4*>(&a[4]) =
                *reinterpret_cast<const float4*>(&As[kk][ty * 8 + 4]);
            *reinterpret_cast<float4*>(&bfr[0]) =
                *reinterpret_cast<const float4*>(&Bs[kk][tx * 4]);
#pragma unroll
            for (int i = 0; i < 8; i++)
#pragma unroll
                for (int j = 0; j < 4; j++) acc[i][j] += a[i] * bfr[j];
        }
        __syncthreads();
    }

    const float qscale = 0.17677669529663687f;  // 1/sqrt(32)

#pragma unroll
    for (int i = 0; i < 8; i++) {
        int m = m0 + ty * 8 + i;
        // row-dependent decode (hoisted by compiler per i)
        int win = m / NTOK, tokn = m % NTOK;
#pragma unroll
        for (int j = 0; j < 4; j++) {
            int n = n0 + tx * 4 + j;
            float v = acc[i][j] + __ldg(&bias[n]);
            if (MODE == 0) {
                int t = n / CCH;                 // constant per block (64 | 384)
                int rem = n - t * CCH;
                int nh = rem >> 5, hd = rem & 31;
                size_t dst = (((size_t)(win * NHEAD + nh)) * NTOK + tokn) * HDIM + hd;
                if (t == 0)      g_q[dst] = v * qscale;
                else if (t == 1) g_k[dst] = v;
                else             g_v[dst] = v;
            } else if (MODE == 1) {
                int b = win >> 6, widx = win & 63;
                int wh = widx >> 3, ww = widx & 7;
                int hp = wh * 7 + tokn / 7;
                int wp = ww * 7 + tokn % 7;
                int h = hp + 3; if (h >= HH)  h -= HH;
                int w = wp + 3; if (w >= WW2) w -= WW2;
                size_t tk = (size_t)(b * HH + h) * WW2 + w;
                g_x2[tk * CCH + n] = v + g_xbhwc[tk * CCH + n];
            } else if (MODE == 2) {
                v = 0.5f * v * (1.0f + erff(v * 0.70710678118654752f));
                g_h1[(size_t)m * MLPD + n] = v;
            } else {
                g_y[(size_t)m * CCH + n] = v + g_x2[(size_t)m * CCH + n];
            }
        }
    }
}

// ---------------------------------------------------------------------------
// K3: windowed attention. One block per (win, head). S = qK^T + mask,
// softmax, O = P V. Mask computed analytically from shifted-region ids.
// ---------------------------------------------------------------------------
__global__ void __launch_bounds__(256) k_attn()
{
    __shared__ float sq[NTOK * 33], sk[NTOK * 33], sv[NTOK * 33];
    __shared__ float sS[NTOK * 52];
    __shared__ int   sid[NTOK];

    const int win = blockIdx.x / NHEAD;
    const int nh  = blockIdx.x % NHEAD;
    const int tid = threadIdx.x;
    const size_t base = ((size_t)(win * NHEAD + nh)) * NTOK * HDIM;

    for (int idx = tid; idx < NTOK * HDIM; idx += 256) {
        int r = idx >> 5, c = idx & 31;
        sq[r * 33 + c] = g_q[base + idx];
        sk[r * 33 + c] = g_k[base + idx];
        sv[r * 33 + c] = g_v[base + idx];
    }
    if (tid < NTOK) {
        int widx = win & 63;
        int wh = widx >> 3, ww = widx & 7;
        int hp = wh * 7 + tid / 7;
        int wp = ww * 7 + tid % 7;
        int hr = (hp < 49) ? 0 : (hp < 53 ? 1 : 2);
        int wr = (wp < 49) ? 0 : (wp < 53 ? 1 : 2);
        sid[tid] = hr * 3 + wr;
    }
    __syncthreads();

    for (int idx = tid; idx < NTOK * NTOK; idx += 256) {
        int i = idx / NTOK, j = idx % NTOK;
        float s = 0.f;
#pragma unroll
        for (int l = 0; l < HDIM; l++) s += sq[i * 33 + l] * sk[j * 33 + l];
        if (sid[i] != sid[j]) s -= 100.0f;
        sS[i * 52 + j] = s;
    }
    __syncthreads();

    const int warp = tid >> 5, lane = tid & 31;
    for (int i = warp; i < NTOK; i += 8) {
        float mx = -1e30f;
        for (int j = lane; j < NTOK; j += 32) mx = fmaxf(mx, sS[i * 52 + j]);
#pragma unroll
        for (int o = 16; o; o >>= 1) mx = fmaxf(mx, __shfl_xor_sync(0xffffffffu, mx, o));
        float sum = 0.f;
        for (int j = lane; j < NTOK; j += 32) {
            float e = __expf(sS[i * 52 + j] - mx);
            sS[i * 52 + j] = e;
            sum += e;
        }
#pragma unroll
        for (int o = 16; o; o >>= 1) sum += __shfl_xor_sync(0xffffffffu, sum, o);
        float inv = 1.0f / sum;
        for (int j = lane; j < NTOK; j += 32) sS[i * 52 + j] *= inv;
    }
    __syncthreads();

    for (int idx = tid; idx < NTOK * HDIM; idx += 256) {
        int i = idx >> 5, d = idx & 31;
        float o = 0.f;
#pragma unroll 7
        for (int j = 0; j < NTOK; j++) o += sS[i * 52 + j] * sv[j * 33 + d];
        g_ao[((size_t)(win * NTOK + i)) * CCH + nh * HDIM + d] = o;
    }
}

// ---------------------------------------------------------------------------
// K4: LN2 — one warp per token, float-strided coalesced loads
// ---------------------------------------------------------------------------
__global__ void __launch_bounds__(256) k_ln2(
    const float* __restrict__ g2, const float* __restrict__ b2)
{
    const int warp = threadIdx.x >> 5, lane = threadIdx.x & 31;
    const size_t tok = (size_t)blockIdx.x * 8 + warp;
    const float* p = g_x2 + tok * CCH;
    float v[12];
    float s = 0.f, s2 = 0.f;
#pragma unroll
    for (int i = 0; i < 12; i++) {
        v[i] = p[lane + i * 32];
        s += v[i]; s2 += v[i] * v[i];
    }
#pragma unroll
    for (int o = 16; o; o >>= 1) {
        s  += __shfl_xor_sync(0xffffffffu, s,  o);
        s2 += __shfl_xor_sync(0xffffffffu, s2, o);
    }
    float mu = s * (1.0f / CCH);
    float rs = rsqrtf(s2 * (1.0f / CCH) - mu * mu + 1e-5f);
    float* q = g_xn2 + tok * CCH;
#pragma unroll
    for (int i = 0; i < 12; i++) {
        int c = lane + i * 32;
        q[c] = (v[i] - mu) * rs * __ldg(&g2[c]) + __ldg(&b2[c]);
    }
}

// ---------------------------------------------------------------------------
// K5: NHWC (token-major) -> NCHW final transpose via smem tile
// ---------------------------------------------------------------------------
__global__ void __launch_bounds__(256) k_tr(float* __restrict__ out)
{
    __shared__ float t[32 * 57];
    const int bh = blockIdx.x;                  // 0..895
    const int c0 = blockIdx.y * 32;             // 0..11 tiles
    const int b = bh / HH, h = bh % HH;
    const float* yp = g_y + (size_t)bh * WW2 * CCH + c0;

    for (int idx = threadIdx.x; idx < WW2 * 32; idx += 256) {
        int w = idx >> 5, cc = idx & 31;
        t[cc * 57 + w] = yp[(size_t)w * CCH + cc];
    }
    __syncthreads();
    float* op = out + (size_t)b * CCH * (HH * WW2) + (size_t)c0 * (HH * WW2) + h * WW2;
    for (int idx = threadIdx.x; idx < WW2 * 32; idx += 256) {
        int cc = idx / WW2, w = idx % WW2;
        op[(size_t)cc * (HH * WW2) + w] = t[cc * 57 + w];
    }
}

// ---------------------------------------------------------------------------
// launch
// ---------------------------------------------------------------------------
extern "C" void kernel_launch(void* const* d_in, const int* in_sizes, int n_in,
                              void* d_out, int out_size)
{
    const float* x       = (const float*)d_in[0];
    const float* norm1_g = (const float*)d_in[1];
    const float* norm1_b = (const float*)d_in[2];
    const float* qkv_w   = (const float*)d_in[3];
    const float* qkv_b   = (const float*)d_in[4];
    const float* proj_w  = (const float*)d_in[5];
    const float* proj_b  = (const float*)d_in[6];
    const float* norm2_g = (const float*)d_in[7];
    const float* norm2_b = (const float*)d_in[8];
    const float* fc1_w   = (const float*)d_in[9];
    const float* fc1_b   = (const float*)d_in[10];
    const float* fc2_w   = (const float*)d_in[11];
    const float* fc2_b   = (const float*)d_in[12];

    float *p_xw, *p_ao, *p_xn2, *p_h1;
    cudaGetSymbolAddress((void**)&p_xw,  g_xw);
    cudaGetSymbolAddress((void**)&p_ao,  g_ao);
    cudaGetSymbolAddress((void**)&p_xn2, g_xn2);
    cudaGetSymbolAddress((void**)&p_h1,  g_h1);

    const int ln1_smem = 384 * 57 * sizeof(float);   // 87552 B
    cudaFuncSetAttribute(k_ln1_window,
                         cudaFuncAttributeMaxDynamicSharedMemorySize, ln1_smem);

    // 1) LN1 + transpose + shifted window partition
    k_ln1_window<<<16 * HH, 256, ln1_smem>>>(x, norm1_g, norm1_b);

    // 2) QKV GEMM: [50176,384] x [384,1152]
    k_gemm<0><<<dim3(1152 / 64, TOK / 128), 256>>>(p_xw, qkv_w, qkv_b,
                                                   TOK, 1152, CCH);

    // 3) windowed attention (12288 head-windows)
    k_attn<<<NWIN * NHEAD, 256>>>();

    // 4) proj GEMM + window reverse + residual
    k_gemm<1><<<dim3(CCH / 64, TOK / 128), 256>>>(p_ao, proj_w, proj_b,
                                                  TOK, CCH, CCH);

    // 5) LN2
    k_ln2<<<TOK / 8, 256>>>(norm2_g, norm2_b);

    // 6) fc1 + GELU: [50176,384] x [384,1536]
    k_gemm<2><<<dim3(MLPD / 64, TOK / 128), 256>>>(p_xn2, fc1_w, fc1_b,
                                                   TOK, MLPD, CCH);

    // 7) fc2 + residual: [50176,1536] x [1536,384]
    k_gemm<3><<<dim3(CCH / 64, TOK / 128), 256>>>(p_h1, fc2_w, fc2_b,
                                                  TOK, CCH, MLPD);

    // 8) NHWC -> NCHW
    k_tr<<<dim3(16 * HH, CCH / 32), 256>>>((float*)d_out);
}

// round 5
// speedup vs baseline: 1.8246x; 1.8246x over previous
#include <cuda_runtime.h>
#include <cuda_bf16.h>
#include <math.h>
#include <stdint.h>

// ---------------------------------------------------------------------------
// Swin block: B=16, C=384, H=W=56, NH=12, WS=7, SS=3, MLP=1536
// GEMMs via mma.sync tf32 (base PTX -> legacy tensor pipe on sm_103)
// ---------------------------------------------------------------------------
#define TOK   50176
#define CCH   384
#define HH    56
#define WW2   56
#define NWIN  1024
#define NTOK  49
#define NHEAD 12
#define HDIM  32
#define MLPD  1536

// Scratch
__device__ float g_xbhwc[TOK * CCH];
__device__ float g_xw   [TOK * CCH];
__device__ float g_q    [TOK * CCH];
__device__ float g_k    [TOK * CCH];
__device__ float g_v    [TOK * CCH];
__device__ float g_ao   [TOK * CCH];
__device__ float g_x2   [TOK * CCH];
__device__ float g_xn2  [TOK * CCH];
__device__ float g_h1   [TOK * MLPD];
__device__ float g_y    [TOK * CCH];

__device__ __forceinline__ float tf32r(float f) {
    uint32_t u;
    asm("cvt.rna.tf32.f32 %0, %1;" : "=r"(u) : "f"(f));
    return __uint_as_float(u);
}

// ---------------------------------------------------------------------------
// tf32 mma.sync GEMM: C[M,N] = A[M,K] * B[K,N], A row-major K-contig,
// B row-major N-contig ([k][n] == what mma wants).
// 128x128 CTA tile, 8 warps (2M x 4N), warp = 64x32, k-chunk 16.
// MODE 0: QKV split  1: proj+winrev+residual  2: fc1+GELU  3: fc2+residual
// ---------------------------------------------------------------------------
template <int MODE>
__global__ void __launch_bounds__(256, 2) k_gemm_mma(
    const float* __restrict__ A, const float* __restrict__ Bw,
    const float* __restrict__ bias, int K, int N, int NC)
{
    __shared__ float As[2][16][132];   // [k][m]
    __shared__ float Bs[2][16][132];   // [k][n]

    const int tid = threadIdx.x;
    const int wid = tid >> 5, lane = tid & 31;
    const int gid = lane >> 2, tig = lane & 3;
    const int wm = wid & 1, wn = wid >> 1;       // 2 x 4 warp grid
    const int m0 = blockIdx.y * 128, n0 = blockIdx.x * 128;

    float acc[4][4][4];
#pragma unroll
    for (int a = 0; a < 4; a++)
#pragma unroll
        for (int b = 0; b < 4; b++)
#pragma unroll
            for (int c = 0; c < 4; c++) acc[a][b][c] = 0.f;

    // per-thread LDG staging
    float4 la[2], lb[2];
    const int rowA = tid >> 1;                  // 2 threads/row? no: see below
    // A: 128 rows x 16 k -> 512 float4; thread handles idx = t*256+tid
    // B: 16 k x 128 n    -> 512 float4

    auto ldg_chunk = [&](int c) {
#pragma unroll
        for (int t = 0; t < 2; t++) {
            int idx = t * 256 + tid;
            int row = idx >> 2, kq = (idx & 3) * 4;
            la[t] = *reinterpret_cast<const float4*>(
                A + (size_t)(m0 + row) * K + c * 16 + kq);
            int kr = idx >> 5, nq = (idx & 31) * 4;
            lb[t] = *reinterpret_cast<const float4*>(
                Bw + (size_t)(c * 16 + kr) * N + n0 + nq);
        }
    };
    auto sts_chunk = [&](int s) {
#pragma unroll
        for (int t = 0; t < 2; t++) {
            int idx = t * 256 + tid;
            int row = idx >> 2, kq = (idx & 3) * 4;
            As[s][kq + 0][row] = tf32r(la[t].x);
            As[s][kq + 1][row] = tf32r(la[t].y);
            As[s][kq + 2][row] = tf32r(la[t].z);
            As[s][kq + 3][row] = tf32r(la[t].w);
            int kr = idx >> 5, nq = (idx & 31) * 4;
            float4 v;
            v.x = tf32r(lb[t].x); v.y = tf32r(lb[t].y);
            v.z = tf32r(lb[t].z); v.w = tf32r(lb[t].w);
            *reinterpret_cast<float4*>(&Bs[s][kr][nq]) = v;
        }
    };
    auto compute = [&](int s) {
#pragma unroll
        for (int ks = 0; ks < 2; ks++) {
            const int kb = ks * 8;
            uint32_t af[4][4], bf[4][2];
#pragma unroll
            for (int mi = 0; mi < 4; mi++) {
                int m = wm * 64 + mi * 16 + gid;
                af[mi][0] = __float_as_uint(As[s][kb + tig][m]);
                af[mi][1] = __float_as_uint(As[s][kb + tig][m + 8]);
                af[mi][2] = __float_as_uint(As[s][kb + tig + 4][m]);
                af[mi][3] = __float_as_uint(As[s][kb + tig + 4][m + 8]);
            }
#pragma unroll
            for (int ni = 0; ni < 4; ni++) {
                int n = wn * 32 + ni * 8 + gid;
                bf[ni][0] = __float_as_uint(Bs[s][kb + tig][n]);
                bf[ni][1] = __float_as_uint(Bs[s][kb + tig + 4][n]);
            }
#pragma unroll
            for (int mi = 0; mi < 4; mi++)
#pragma unroll
                for (int ni = 0; ni < 4; ni++)
                    asm volatile(
                        "mma.sync.aligned.m16n8k8.row.col.f32.tf32.tf32.f32 "
                        "{%0,%1,%2,%3},{%4,%5,%6,%7},{%8,%9},{%0,%1,%2,%3};"
                        : "+f"(acc[mi][ni][0]), "+f"(acc[mi][ni][1]),
                          "+f"(acc[mi][ni][2]), "+f"(acc[mi][ni][3])
                        : "r"(af[mi][0]), "r"(af[mi][1]),
                          "r"(af[mi][2]), "r"(af[mi][3]),
                          "r"(bf[ni][0]), "r"(bf[ni][1]));
        }
    };

    int s = 0;
    ldg_chunk(0);
    sts_chunk(0);
    __syncthreads();
    for (int c = 0; c < NC; c++) {
        if (c + 1 < NC) ldg_chunk(c + 1);
        compute(s);
        if (c + 1 < NC) sts_chunk(s ^ 1);
        __syncthreads();
        s ^= 1;
    }

    // ---------------- epilogue: fused scatter from accumulators -------------
    const float qscale = 0.17677669529663687f;

    auto store_pair = [&](int m, int n, float vx, float vy) {
        vx += __ldg(&bias[n]);
        vy += __ldg(&bias[n + 1]);
        if (MODE == 0) {
            int tq = n / CCH;
            int rem = n - tq * CCH;
            int head = rem >> 5, hd = rem & 31;
            int win = m / NTOK, tokn = m - win * NTOK;
            float scl = (tq == 0) ? qscale : 1.0f;
            float* dst = (tq == 0) ? g_q : (tq == 1) ? g_k : g_v;
            size_t o = (((size_t)(win * NHEAD + head)) * NTOK + tokn) * HDIM + hd;
            float2 v = make_float2(vx * scl, vy * scl);
            *reinterpret_cast<float2*>(dst + o) = v;
        } else if (MODE == 1) {
            int win = m / NTOK, tokn = m - win * NTOK;
            int b = win >> 6, widx = win & 63;
            int h = (widx >> 3) * 7 + tokn / 7 + 3; if (h >= HH)  h -= HH;
            int w = (widx & 7) * 7 + tokn % 7 + 3;  if (w >= WW2) w -= WW2;
            size_t tk = ((size_t)(b * HH + h)) * WW2 + w;
            float2 r = *reinterpret_cast<const float2*>(g_xbhwc + tk * CCH + n);
            float2 v = make_float2(vx + r.x, vy + r.y);
            *reinterpret_cast<float2*>(g_x2 + tk * CCH + n) = v;
        } else if (MODE == 2) {
            vx = 0.5f * vx * (1.0f + erff(vx * 0.70710678118654752f));
            vy = 0.5f * vy * (1.0f + erff(vy * 0.70710678118654752f));
            *reinterpret_cast<float2*>(g_h1 + (size_t)m * MLPD + n) =
                make_float2(vx, vy);
        } else {
            float2 r = *reinterpret_cast<const float2*>(g_x2 + (size_t)m * CCH + n);
            *reinterpret_cast<float2*>(g_y + (size_t)m * CCH + n) =
                make_float2(vx + r.x, vy + r.y);
        }
    };

#pragma unroll
    for (int mi = 0; mi < 4; mi++) {
#pragma unroll
        for (int ni = 0; ni < 4; ni++) {
            int m = m0 + wm * 64 + mi * 16 + gid;
            int n = n0 + wn * 32 + ni * 8 + tig * 2;
            store_pair(m,     n, acc[mi][ni][0], acc[mi][ni][1]);
            store_pair(m + 8, n, acc[mi][ni][2], acc[mi][ni][3]);
        }
    }
}

// ---------------------------------------------------------------------------
// K1: LN1 + NCHW->NHWC + shifted-window partition
// ---------------------------------------------------------------------------
__global__ void __launch_bounds__(256) k_ln1_window(
    const float* __restrict__ x, const float* __restrict__ g1,
    const float* __restrict__ b1)
{
    extern __shared__ float sm[];
    __shared__ float smu[56], srs[56];
    const int bh = blockIdx.x;
    const int b = bh / HH, h = bh % HH;
    const int tid = threadIdx.x;
    const float* xp = x + (size_t)b * CCH * (HH * WW2) + (size_t)h * WW2;

    for (int idx = tid; idx < CCH * WW2; idx += 256) {
        int c = idx / WW2, w = idx % WW2;
        sm[c * 57 + w] = xp[(size_t)c * (HH * WW2) + w];
    }
    __syncthreads();
    if (tid < WW2) {
        float s = 0.f, s2 = 0.f;
        for (int c = 0; c < CCH; c++) {
            float t = sm[c * 57 + tid];
            s += t; s2 += t * t;
        }
        float mu = s * (1.0f / CCH);
        smu[tid] = mu;
        srs[tid] = rsqrtf(s2 * (1.0f / CCH) - mu * mu + 1e-5f);
    }
    __syncthreads();

    int hp = h - 3; if (hp < 0) hp += HH;
    const int wh = hp / 7, rr = hp % 7;
    for (int idx = tid; idx < WW2 * CCH; idx += 256) {
        int w = idx / CCH, c = idx % CCH;
        float val = sm[c * 57 + w];
        size_t tok = (size_t)(b * HH + h) * WW2 + w;
        g_xbhwc[tok * CCH + c] = val;
        float nv = (val - smu[w]) * srs[w] * __ldg(&g1[c]) + __ldg(&b1[c]);
        int wp = w - 3; if (wp < 0) wp += WW2;
        int win = (b * 8 + wh) * 8 + wp / 7;
        g_xw[((size_t)win * NTOK + rr * 7 + wp % 7) * CCH + c] = nv;
    }
}

// ---------------------------------------------------------------------------
// K3: windowed attention
// ---------------------------------------------------------------------------
__global__ void __launch_bounds__(256) k_attn()
{
    __shared__ float sq[NTOK * 33], sk[NTOK * 33], sv[NTOK * 33];
    __shared__ float sS[NTOK * 52];
    __shared__ int   sid[NTOK];

    const int win = blockIdx.x / NHEAD;
    const int nh  = blockIdx.x % NHEAD;
    const int tid = threadIdx.x;
    const size_t base = ((size_t)(win * NHEAD + nh)) * NTOK * HDIM;

    for (int idx = tid; idx < NTOK * HDIM; idx += 256) {
        int r = idx >> 5, c = idx & 31;
        sq[r * 33 + c] = g_q[base + idx];
        sk[r * 33 + c] = g_k[base + idx];
        sv[r * 33 + c] = g_v[base + idx];
    }
    if (tid < NTOK) {
        int widx = win & 63;
        int hp = (widx >> 3) * 7 + tid / 7;
        int wp = (widx & 7) * 7 + tid % 7;
        int hr = (hp < 49) ? 0 : (hp < 53 ? 1 : 2);
        int wr = (wp < 49) ? 0 : (wp < 53 ? 1 : 2);
        sid[tid] = hr * 3 + wr;
    }
    __syncthreads();

    for (int idx = tid; idx < NTOK * NTOK; idx += 256) {
        int i = idx / NTOK, j = idx % NTOK;
        float s = 0.f;
#pragma unroll
        for (int l = 0; l < HDIM; l++) s += sq[i * 33 + l] * sk[j * 33 + l];
        if (sid[i] != sid[j]) s -= 100.0f;
        sS[i * 52 + j] = s;
    }
    __syncthreads();

    const int warp = tid >> 5, lane = tid & 31;
    for (int i = warp; i < NTOK; i += 8) {
        float mx = -1e30f;
        for (int j = lane; j < NTOK; j += 32) mx = fmaxf(mx, sS[i * 52 + j]);
#pragma unroll
        for (int o = 16; o; o >>= 1) mx = fmaxf(mx, __shfl_xor_sync(0xffffffffu, mx, o));
        float sum = 0.f;
        for (int j = lane; j < NTOK; j += 32) {
            float e = __expf(sS[i * 52 + j] - mx);
            sS[i * 52 + j] = e;
            sum += e;
        }
#pragma unroll
        for (int o = 16; o; o >>= 1) sum += __shfl_xor_sync(0xffffffffu, sum, o);
        float inv = 1.0f / sum;
        for (int j = lane; j < NTOK; j += 32) sS[i * 52 + j] *= inv;
    }
    __syncthreads();

    for (int idx = tid; idx < NTOK * HDIM; idx += 256) {
        int i = idx >> 5, d = idx & 31;
        float o = 0.f;
#pragma unroll 7
        for (int j = 0; j < NTOK; j++) o += sS[i * 52 + j] * sv[j * 33 + d];
        g_ao[((size_t)(win * NTOK + i)) * CCH + nh * HDIM + d] = o;
    }
}

// ---------------------------------------------------------------------------
// K4: LN2
// ---------------------------------------------------------------------------
__global__ void __launch_bounds__(256) k_ln2(
    const float* __restrict__ g2, const float* __restrict__ b2)
{
    const int warp = threadIdx.x >> 5, lane = threadIdx.x & 31;
    const size_t tok = (size_t)blockIdx.x * 8 + warp;
    const float* p = g_x2 + tok * CCH;
    float v[12];
    float s = 0.f, s2 = 0.f;
#pragma unroll
    for (int i = 0; i < 12; i++) {
        v[i] = p[lane + i * 32];
        s += v[i]; s2 += v[i] * v[i];
    }
#pragma unroll
    for (int o = 16; o; o >>= 1) {
        s  += __shfl_xor_sync(0xffffffffu, s,  o);
        s2 += __shfl_xor_sync(0xffffffffu, s2, o);
    }
    float mu = s * (1.0f / CCH);
    float rs = rsqrtf(s2 * (1.0f / CCH) - mu * mu + 1e-5f);
    float* q = g_xn2 + tok * CCH;
#pragma unroll
    for (int i = 0; i < 12; i++) {
        int c = lane + i * 32;
        q[c] = (v[i] - mu) * rs * __ldg(&g2[c]) + __ldg(&b2[c]);
    }
}

// ---------------------------------------------------------------------------
// K5: NHWC -> NCHW
// ---------------------------------------------------------------------------
__global__ void __launch_bounds__(256) k_tr(float* __restrict__ out)
{
    __shared__ float t[32 * 57];
    const int bh = blockIdx.x;
    const int c0 = blockIdx.y * 32;
    const int b = bh / HH, h = bh % HH;
    const float* yp = g_y + (size_t)bh * WW2 * CCH + c0;

    for (int idx = threadIdx.x; idx < WW2 * 32; idx += 256) {
        int w = idx >> 5, cc = idx & 31;
        t[cc * 57 + w] = yp[(size_t)w * CCH + cc];
    }
    __syncthreads();
    float* op = out + (size_t)b * CCH * (HH * WW2) + (size_t)c0 * (HH * WW2) + h * WW2;
    for (int idx = threadIdx.x; idx < WW2 * 32; idx += 256) {
        int cc = idx / WW2, w = idx % WW2;
        op[(size_t)cc * (HH * WW2) + w] = t[cc * 57 + w];
    }
}

// ---------------------------------------------------------------------------
extern "C" void kernel_launch(void* const* d_in, const int* in_sizes, int n_in,
                              void* d_out, int out_size)
{
    const float* x       = (const float*)d_in[0];
    const float* norm1_g = (const float*)d_in[1];
    const float* norm1_b = (const float*)d_in[2];
    const float* qkv_w   = (const float*)d_in[3];
    const float* qkv_b   = (const float*)d_in[4];
    const float* proj_w  = (const float*)d_in[5];
    const float* proj_b  = (const float*)d_in[6];
    const float* norm2_g = (const float*)d_in[7];
    const float* norm2_b = (const float*)d_in[8];
    const float* fc1_w   = (const float*)d_in[9];
    const float* fc1_b   = (const float*)d_in[10];
    const float* fc2_w   = (const float*)d_in[11];
    const float* fc2_b   = (const float*)d_in[12];

    float *p_xw, *p_ao, *p_xn2, *p_h1;
    cudaGetSymbolAddress((void**)&p_xw,  g_xw);
    cudaGetSymbolAddress((void**)&p_ao,  g_ao);
    cudaGetSymbolAddress((void**)&p_xn2, g_xn2);
    cudaGetSymbolAddress((void**)&p_h1,  g_h1);

    const int ln1_smem = 384 * 57 * sizeof(float);
    cudaFuncSetAttribute(k_ln1_window,
                         cudaFuncAttributeMaxDynamicSharedMemorySize, ln1_smem);

    // 1) LN1 + transpose + shifted window partition
    k_ln1_window<<<16 * HH, 256, ln1_smem>>>(x, norm1_g, norm1_b);

    // 2) QKV GEMM: [50176,384] x [384,1152]
    k_gemm_mma<0><<<dim3(1152 / 128, TOK / 128), 256>>>(
        p_xw, qkv_w, qkv_b, 384, 1152, 24);

    // 3) windowed attention
    k_attn<<<NWIN * NHEAD, 256>>>();

    // 4) proj GEMM + window reverse + residual
    k_gemm_mma<1><<<dim3(CCH / 128, TOK / 128), 256>>>(
        p_ao, proj_w, proj_b, 384, CCH, 24);

    // 5) LN2
    k_ln2<<<TOK / 8, 256>>>(norm2_g, norm2_b);

    // 6) fc1 + GELU
    k_gemm_mma<2><<<dim3(MLPD / 128, TOK / 128), 256>>>(
        p_xn2, fc1_w, fc1_b, 384, MLPD, 24);

    // 7) fc2 + residual
    k_gemm_mma<3><<<dim3(CCH / 128, TOK / 128), 256>>>(
        p_h1, fc2_w, fc2_b, 1536, CCH, 96);

    // 8) NHWC -> NCHW
    k_tr<<<dim3(16 * HH, CCH / 32), 256>>>((float*)d_out);
}

// round 6
// speedup vs baseline: 1.9929x; 1.0922x over previous
#include <cuda_runtime.h>
#include <cuda_bf16.h>
#include <math.h>
#include <stdint.h>

// ---------------------------------------------------------------------------
// Swin block: B=16, C=384, H=W=56, NH=12, WS=7, SS=3, MLP=1536
// GEMMs via mma.sync tf32 with crosswise smem (1-wavefront fragment loads)
// ---------------------------------------------------------------------------
#define TOK   50176
#define CCH   384
#define HH    56
#define WW2   56
#define NWIN  1024
#define NTOK  49
#define NHEAD 12
#define HDIM  32
#define MLPD  1536

// Scratch
__device__ float g_xbhwc[TOK * CCH];
__device__ float g_xw   [TOK * CCH];
__device__ float g_q    [TOK * CCH];
__device__ float g_k    [TOK * CCH];
__device__ float g_v    [TOK * CCH];
__device__ float g_ao   [TOK * CCH];
__device__ float g_x2   [TOK * CCH];
__device__ float g_xn2  [TOK * CCH];
__device__ float g_h1   [TOK * MLPD];
__device__ float g_y    [TOK * CCH];

__device__ __forceinline__ float tf32r(float f) {
    uint32_t u;
    asm("cvt.rna.tf32.f32 %0, %1;" : "=r"(u) : "f"(f));
    return __uint_as_float(u);
}

// ---------------------------------------------------------------------------
// tf32 mma.sync GEMM: C[M,N] = A[M,K] * B[K,N].
// 128x128 CTA tile, 8 warps (2M x 4N), warp = 64x32, k-chunk 16.
// Crosswise smem: element (k, x) lives at [k>>2][x][k&3]  (16B per x).
//  -> every fragment LDS.32 is one contiguous 128B wavefront.
// MODE 0: QKV split  1: proj+winrev+residual  2: fc1+GELU  3: fc2+residual
// ---------------------------------------------------------------------------
template <int MODE>
__global__ void __launch_bounds__(256, 2) k_gemm_mma(
    const float* __restrict__ A, const float* __restrict__ Bw,
    const float* __restrict__ bias, int K, int N, int NC)
{
    // [stage][kgroup][x][4]
    __shared__ float As[2][4][128][4];
    __shared__ float Bs[2][4][128][4];

    const int tid = threadIdx.x;
    const int wid = tid >> 5, lane = tid & 31;
    const int gid = lane >> 2, tig = lane & 3;
    const int wm = wid & 1, wn = wid >> 1;       // 2 x 4 warp grid
    const int m0 = blockIdx.y * 128, n0 = blockIdx.x * 128;

    float acc[4][4][4];
#pragma unroll
    for (int a = 0; a < 4; a++)
#pragma unroll
        for (int b = 0; b < 4; b++)
#pragma unroll
            for (int c = 0; c < 4; c++) acc[a][b][c] = 0.f;

    // ---- global load staging ----
    // A: idx = t*256+tid, row = idx>>2 (m), kq = (idx&3)*4  -> LDG.128
    const int a_row = tid >> 2, a_kq = (tid & 3) * 4;
    // B: idx in [0,512): n = idx&127, kq = (idx>>7)*4 -> 4 x LDG.32 (coalesced)
    const int b_n0i = tid & 127, b_kq0 = (tid >> 7) * 4;

    float4 la[2];
    float  lb[2][4];

    auto ldg_chunk = [&](int c) {
#pragma unroll
        for (int t = 0; t < 2; t++) {
            int row = t * 64 + a_row;
            la[t] = *reinterpret_cast<const float4*>(
                A + (size_t)(m0 + row) * K + c * 16 + a_kq);
            int kq = t * 8 + b_kq0;
#pragma unroll
            for (int j = 0; j < 4; j++)
                lb[t][j] = __ldg(Bw + (size_t)(c * 16 + kq + j) * N + n0 + b_n0i);
        }
    };
    auto sts_chunk = [&](int s) {
#pragma unroll
        for (int t = 0; t < 2; t++) {
            int row = t * 64 + a_row;
            float4 va;
            va.x = tf32r(la[t].x); va.y = tf32r(la[t].y);
            va.z = tf32r(la[t].z); va.w = tf32r(la[t].w);
            *reinterpret_cast<float4*>(&As[s][a_kq >> 2][row][0]) = va;
            int kq = t * 8 + b_kq0;
            float4 vb;
            vb.x = tf32r(lb[t][0]); vb.y = tf32r(lb[t][1]);
            vb.z = tf32r(lb[t][2]); vb.w = tf32r(lb[t][3]);
            *reinterpret_cast<float4*>(&Bs[s][kq >> 2][b_n0i][0]) = vb;
        }
    };

    const int ma = wm * 64 + gid;       // base m within tile (frag row)
    const int na = wn * 32 + gid;       // base n within tile

    auto compute = [&](int s) {
#pragma unroll
        for (int ks = 0; ks < 2; ks++) {
            const int kg = ks * 2;      // kgroup of k = kb..kb+3
            uint32_t af[4][4], bf[4][2];
#pragma unroll
            for (int mi = 0; mi < 4; mi++) {
                int m = ma + mi * 16;
                af[mi][0] = __float_as_uint(As[s][kg][m][tig]);
                af[mi][1] = __float_as_uint(As[s][kg][m + 8][tig]);
                af[mi][2] = __float_as_uint(As[s][kg + 1][m][tig]);
                af[mi][3] = __float_as_uint(As[s][kg + 1][m + 8][tig]);
            }
#pragma unroll
            for (int ni = 0; ni < 4; ni++) {
                int n = na + ni * 8;
                bf[ni][0] = __float_as_uint(Bs[s][kg][n][tig]);
                bf[ni][1] = __float_as_uint(Bs[s][kg + 1][n][tig]);
            }
#pragma unroll
            for (int mi = 0; mi < 4; mi++)
#pragma unroll
                for (int ni = 0; ni < 4; ni++)
                    asm volatile(
                        "mma.sync.aligned.m16n8k8.row.col.f32.tf32.tf32.f32 "
                        "{%0,%1,%2,%3},{%4,%5,%6,%7},{%8,%9},{%0,%1,%2,%3};"
                        : "+f"(acc[mi][ni][0]), "+f"(acc[mi][ni][1]),
                          "+f"(acc[mi][ni][2]), "+f"(acc[mi][ni][3])
                        : "r"(af[mi][0]), "r"(af[mi][1]),
                          "r"(af[mi][2]), "r"(af[mi][3]),
                          "r"(bf[ni][0]), "r"(bf[ni][1]));
        }
    };

    int s = 0;
    ldg_chunk(0);
    sts_chunk(0);
    __syncthreads();
    for (int c = 0; c < NC; c++) {
        if (c + 1 < NC) ldg_chunk(c + 1);
        compute(s);
        if (c + 1 < NC) sts_chunk(s ^ 1);
        __syncthreads();
        s ^= 1;
    }

    // ---------------- epilogue: fused scatter from accumulators -------------
    const float qscale = 0.17677669529663687f;

    auto store_pair = [&](int m, int n, float vx, float vy) {
        vx += __ldg(&bias[n]);
        vy += __ldg(&bias[n + 1]);
        if (MODE == 0) {
            int tq = n / CCH;
            int rem = n - tq * CCH;
            int head = rem >> 5, hd = rem & 31;
            int win = m / NTOK, tokn = m - win * NTOK;
            float scl = (tq == 0) ? qscale : 1.0f;
            float* dst = (tq == 0) ? g_q : (tq == 1) ? g_k : g_v;
            size_t o = (((size_t)(win * NHEAD + head)) * NTOK + tokn) * HDIM + hd;
            *reinterpret_cast<float2*>(dst + o) = make_float2(vx * scl, vy * scl);
        } else if (MODE == 1) {
            int win = m / NTOK, tokn = m - win * NTOK;
            int b = win >> 6, widx = win & 63;
            int h = (widx >> 3) * 7 + tokn / 7 + 3; if (h >= HH)  h -= HH;
            int w = (widx & 7) * 7 + tokn % 7 + 3;  if (w >= WW2) w -= WW2;
            size_t tk = ((size_t)(b * HH + h)) * WW2 + w;
            float2 r = *reinterpret_cast<const float2*>(g_xbhwc + tk * CCH + n);
            *reinterpret_cast<float2*>(g_x2 + tk * CCH + n) =
                make_float2(vx + r.x, vy + r.y);
        } else if (MODE == 2) {
            vx = 0.5f * vx * (1.0f + erff(vx * 0.70710678118654752f));
            vy = 0.5f * vy * (1.0f + erff(vy * 0.70710678118654752f));
            *reinterpret_cast<float2*>(g_h1 + (size_t)m * MLPD + n) =
                make_float2(vx, vy);
        } else {
            float2 r = *reinterpret_cast<const float2*>(g_x2 + (size_t)m * CCH + n);
            *reinterpret_cast<float2*>(g_y + (size_t)m * CCH + n) =
                make_float2(vx + r.x, vy + r.y);
        }
    };

#pragma unroll
    for (int mi = 0; mi < 4; mi++) {
#pragma unroll
        for (int ni = 0; ni < 4; ni++) {
            int m = m0 + wm * 64 + mi * 16 + gid;
            int n = n0 + wn * 32 + ni * 8 + tig * 2;
            store_pair(m,     n, acc[mi][ni][0], acc[mi][ni][1]);
            store_pair(m + 8, n, acc[mi][ni][2], acc[mi][ni][3]);
        }
    }
}

// ---------------------------------------------------------------------------
// K1: LN1 + NCHW->NHWC + shifted-window partition
// ---------------------------------------------------------------------------
__global__ void __launch_bounds__(256) k_ln1_window(
    const float* __restrict__ x, const float* __restrict__ g1,
    const float* __restrict__ b1)
{
    extern __shared__ float sm[];
    __shared__ float smu[56], srs[56];
    const int bh = blockIdx.x;
    const int b = bh / HH, h = bh % HH;
    const int tid = threadIdx.x;
    const float* xp = x + (size_t)b * CCH * (HH * WW2) + (size_t)h * WW2;

    for (int idx = tid; idx < CCH * WW2; idx += 256) {
        int c = idx / WW2, w = idx % WW2;
        sm[c * 57 + w] = xp[(size_t)c * (HH * WW2) + w];
    }
    __syncthreads();
    if (tid < WW2) {
        float s = 0.f, s2 = 0.f;
        for (int c = 0; c < CCH; c++) {
            float t = sm[c * 57 + tid];
            s += t; s2 += t * t;
        }
        float mu = s * (1.0f / CCH);
        smu[tid] = mu;
        srs[tid] = rsqrtf(s2 * (1.0f / CCH) - mu * mu + 1e-5f);
    }
    __syncthreads();

    int hp = h - 3; if (hp < 0) hp += HH;
    const int wh = hp / 7, rr = hp % 7;
    for (int idx = tid; idx < WW2 * CCH; idx += 256) {
        int w = idx / CCH, c = idx % CCH;
        float val = sm[c * 57 + w];
        size_t tok = (size_t)(b * HH + h) * WW2 + w;
        g_xbhwc[tok * CCH + c] = val;
        float nv = (val - smu[w]) * srs[w] * __ldg(&g1[c]) + __ldg(&b1[c]);
        int wp = w - 3; if (wp < 0) wp += WW2;
        int win = (b * 8 + wh) * 8 + wp / 7;
        g_xw[((size_t)win * NTOK + rr * 7 + wp % 7) * CCH + c] = nv;
    }
}

// ---------------------------------------------------------------------------
// K3: windowed attention
// ---------------------------------------------------------------------------
__global__ void __launch_bounds__(256) k_attn()
{
    __shared__ float sq[NTOK * 33], sk[NTOK * 33], sv[NTOK * 33];
    __shared__ float sS[NTOK * 52];
    __shared__ int   sid[NTOK];

    const int win = blockIdx.x / NHEAD;
    const int nh  = blockIdx.x % NHEAD;
    const int tid = threadIdx.x;
    const size_t base = ((size_t)(win * NHEAD + nh)) * NTOK * HDIM;

    for (int idx = tid; idx < NTOK * HDIM; idx += 256) {
        int r = idx >> 5, c = idx & 31;
        sq[r * 33 + c] = g_q[base + idx];
        sk[r * 33 + c] = g_k[base + idx];
        sv[r * 33 + c] = g_v[base + idx];
    }
    if (tid < NTOK) {
        int widx = win & 63;
        int hp = (widx >> 3) * 7 + tid / 7;
        int wp = (widx & 7) * 7 + tid % 7;
        int hr = (hp < 49) ? 0 : (hp < 53 ? 1 : 2);
        int wr = (wp < 49) ? 0 : (wp < 53 ? 1 : 2);
        sid[tid] = hr * 3 + wr;
    }
    __syncthreads();

    for (int idx = tid; idx < NTOK * NTOK; idx += 256) {
        int i = idx / NTOK, j = idx % NTOK;
        float s = 0.f;
#pragma unroll
        for (int l = 0; l < HDIM; l++) s += sq[i * 33 + l] * sk[j * 33 + l];
        if (sid[i] != sid[j]) s -= 100.0f;
        sS[i * 52 + j] = s;
    }
    __syncthreads();

    const int warp = tid >> 5, lane = tid & 31;
    for (int i = warp; i < NTOK; i += 8) {
        float mx = -1e30f;
        for (int j = lane; j < NTOK; j += 32) mx = fmaxf(mx, sS[i * 52 + j]);
#pragma unroll
        for (int o = 16; o; o >>= 1) mx = fmaxf(mx, __shfl_xor_sync(0xffffffffu, mx, o));
        float sum = 0.f;
        for (int j = lane; j < NTOK; j += 32) {
            float e = __expf(sS[i * 52 + j] - mx);
            sS[i * 52 + j] = e;
            sum += e;
        }
#pragma unroll
        for (int o = 16; o; o >>= 1) sum += __shfl_xor_sync(0xffffffffu, sum, o);
        float inv = 1.0f / sum;
        for (int j = lane; j < NTOK; j += 32) sS[i * 52 + j] *= inv;
    }
    __syncthreads();

    for (int idx = tid; idx < NTOK * HDIM; idx += 256) {
        int i = idx >> 5, d = idx & 31;
        float o = 0.f;
#pragma unroll 7
        for (int j = 0; j < NTOK; j++) o += sS[i * 52 + j] * sv[j * 33 + d];
        g_ao[((size_t)(win * NTOK + i)) * CCH + nh * HDIM + d] = o;
    }
}

// ---------------------------------------------------------------------------
// K4: LN2
// ---------------------------------------------------------------------------
__global__ void __launch_bounds__(256) k_ln2(
    const float* __restrict__ g2, const float* __restrict__ b2)
{
    const int warp = threadIdx.x >> 5, lane = threadIdx.x & 31;
    const size_t tok = (size_t)blockIdx.x * 8 + warp;
    const float* p = g_x2 + tok * CCH;
    float v[12];
    float s = 0.f, s2 = 0.f;
#pragma unroll
    for (int i = 0; i < 12; i++) {
        v[i] = p[lane + i * 32];
        s += v[i]; s2 += v[i] * v[i];
    }
#pragma unroll
    for (int o = 16; o; o >>= 1) {
        s  += __shfl_xor_sync(0xffffffffu, s,  o);
        s2 += __shfl_xor_sync(0xffffffffu, s2, o);
    }
    float mu = s * (1.0f / CCH);
    float rs = rsqrtf(s2 * (1.0f / CCH) - mu * mu + 1e-5f);
    float* q = g_xn2 + tok * CCH;
#pragma unroll
    for (int i = 0; i < 12; i++) {
        int c = lane + i * 32;
        q[c] = (v[i] - mu) * rs * __ldg(&g2[c]) + __ldg(&b2[c]);
    }
}

// ---------------------------------------------------------------------------
// K5: NHWC -> NCHW
// ---------------------------------------------------------------------------
__global__ void __launch_bounds__(256) k_tr(float* __restrict__ out)
{
    __shared__ float t[32 * 57];
    const int bh = blockIdx.x;
    const int c0 = blockIdx.y * 32;
    const int b = bh / HH, h = bh % HH;
    const float* yp = g_y + (size_t)bh * WW2 * CCH + c0;

    for (int idx = threadIdx.x; idx < WW2 * 32; idx += 256) {
        int w = idx >> 5, cc = idx & 31;
        t[cc * 57 + w] = yp[(size_t)w * CCH + cc];
    }
    __syncthreads();
    float* op = out + (size_t)b * CCH * (HH * WW2) + (size_t)c0 * (HH * WW2) + h * WW2;
    for (int idx = threadIdx.x; idx < WW2 * 32; idx += 256) {
        int cc = idx / WW2, w = idx % WW2;
        op[(size_t)cc * (HH * WW2) + w] = t[cc * 57 + w];
    }
}

// ---------------------------------------------------------------------------
extern "C" void kernel_launch(void* const* d_in, const int* in_sizes, int n_in,
                              void* d_out, int out_size)
{
    const float* x       = (const float*)d_in[0];
    const float* norm1_g = (const float*)d_in[1];
    const float* norm1_b = (const float*)d_in[2];
    const float* qkv_w   = (const float*)d_in[3];
    const float* qkv_b   = (const float*)d_in[4];
    const float* proj_w  = (const float*)d_in[5];
    const float* proj_b  = (const float*)d_in[6];
    const float* norm2_g = (const float*)d_in[7];
    const float* norm2_b = (const float*)d_in[8];
    const float* fc1_w   = (const float*)d_in[9];
    const float* fc1_b   = (const float*)d_in[10];
    const float* fc2_w   = (const float*)d_in[11];
    const float* fc2_b   = (const float*)d_in[12];

    float *p_xw, *p_ao, *p_xn2, *p_h1;
    cudaGetSymbolAddress((void**)&p_xw,  g_xw);
    cudaGetSymbolAddress((void**)&p_ao,  g_ao);
    cudaGetSymbolAddress((void**)&p_xn2, g_xn2);
    cudaGetSymbolAddress((void**)&p_h1,  g_h1);

    const int ln1_smem = 384 * 57 * sizeof(float);
    cudaFuncSetAttribute(k_ln1_window,
                         cudaFuncAttributeMaxDynamicSharedMemorySize, ln1_smem);

    // 1) LN1 + transpose + shifted window partition
    k_ln1_window<<<16 * HH, 256, ln1_smem>>>(x, norm1_g, norm1_b);

    // 2) QKV GEMM: [50176,384] x [384,1152]
    k_gemm_mma<0><<<dim3(1152 / 128, TOK / 128), 256>>>(
        p_xw, qkv_w, qkv_b, 384, 1152, 24);

    // 3) windowed attention
    k_attn<<<NWIN * NHEAD, 256>>>();

    // 4) proj GEMM + window reverse + residual
    k_gemm_mma<1><<<dim3(CCH / 128, TOK / 128), 256>>>(
        p_ao, proj_w, proj_b, 384, CCH, 24);

    // 5) LN2
    k_ln2<<<TOK / 8, 256>>>(norm2_g, norm2_b);

    // 6) fc1 + GELU
    k_gemm_mma<2><<<dim3(MLPD / 128, TOK / 128), 256>>>(
        p_xn2, fc1_w, fc1_b, 384, MLPD, 24);

    // 7) fc2 + residual
    k_gemm_mma<3><<<dim3(CCH / 128, TOK / 128), 256>>>(
        p_h1, fc2_w, fc2_b, 1536, CCH, 96);

    // 8) NHWC -> NCHW
    k_tr<<<dim3(16 * HH, CCH / 32), 256>>>((float*)d_out);
}